// round 4
// baseline (speedup 1.0000x reference)
#include <cuda_runtime.h>
#include <cuda_bf16.h>

#define NHEADS 512
#define NK     64
#define SEQ    2048
#define NFFT   4096
#define NB     16
#define PITCH  272   // transpose pitch: 16*17, conflict-free for both patterns

typedef unsigned long long ull;

// Filter spectra, packed complex (lo=re, hi=im), layout [h][q*256+t]
__device__ ull d_Fhat[NHEADS * NFFT];

// ---------------------------------------------------------------------------
// Packed f32x2 complex helpers (value = ull, lo 32b = re, hi 32b = im)
// ---------------------------------------------------------------------------
__device__ __forceinline__ ull pk2(float x, float y) {
    ull r; asm("mov.b64 %0, {%1, %2};" : "=l"(r) : "f"(x), "f"(y)); return r;
}
__device__ __forceinline__ void unpk2(ull a, float& x, float& y) {
    asm("mov.b64 {%0, %1}, %2;" : "=f"(x), "=f"(y) : "l"(a));
}
__device__ __forceinline__ ull padd(ull a, ull b) {
    ull r; asm("add.rn.f32x2 %0, %1, %2;" : "=l"(r) : "l"(a), "l"(b)); return r;
}
__device__ __forceinline__ ull psub(ull a, ull b) {   // a - b  via fma(b, -1, a)
    const ull m1 = 0xBF800000BF800000ULL;
    ull r; asm("fma.rn.f32x2 %0, %1, %2, %3;" : "=l"(r) : "l"(b), "l"(m1), "l"(a)); return r;
}
__device__ __forceinline__ float fneg(float x) {
    return __int_as_float(__float_as_int(x) ^ 0x80000000);
}
// multiply by -i (fwd) or +i (inv)
template<int INV>
__device__ __forceinline__ ull pmulj(ull a) {
    float x, y; unpk2(a, x, y);
    return INV ? pk2(fneg(y), x) : pk2(y, fneg(x));
}
// packed a times scalar complex (wx, wy)
__device__ __forceinline__ ull pcmulf(ull a, float wx, float wy) {
    float x, y; unpk2(a, x, y);
    return pk2(fmaf(x, wx, -(y * wy)), fmaf(x, wy, y * wx));
}

template<int INV>
__device__ __forceinline__ void bfly4p(ull& x0, ull& x1, ull& x2, ull& x3) {
    ull ac = padd(x0, x2), amc = psub(x0, x2);
    ull bd = padd(x1, x3), bmd = psub(x1, x3);
    ull jb = pmulj<INV>(bmd);
    x0 = padd(ac, bd);  x2 = psub(ac, bd);
    x1 = padd(amc, jb); x3 = psub(amc, jb);
}

// twiddle application W16^{n1*k1} for dft16 (sign via INV)
template<int INV>
__device__ __forceinline__ void tw16(ull* u) {
    const float C1 = 0.9238795325112867f, S1 = 0.3826834323650898f, R = 0.7071067811865476f;
    const float s = INV ? 1.0f : -1.0f;
    u[5]  = pcmulf(u[5],   C1,  s * S1);
    u[6]  = pcmulf(u[6],    R,  s * R);
    u[7]  = pcmulf(u[7],   S1,  s * C1);
    u[9]  = pcmulf(u[9],    R,  s * R);
    u[10] = pmulj<INV>(u[10]);
    u[11] = pcmulf(u[11],  -R,  s * R);
    u[13] = pcmulf(u[13],  S1,  s * C1);
    u[14] = pcmulf(u[14],  -R,  s * R);
    u[15] = pcmulf(u[15], -C1, -s * S1);
}

// Full in-place 16-pt DFT (x[n] -> X[k] at x[k]); INV=1 un-normalized inverse.
template<int INV>
__device__ __forceinline__ void dft16p(ull* x) {
    ull u[16];
    #pragma unroll
    for (int n1 = 0; n1 < 4; n1++) {
        ull a = x[n1], b = x[n1 + 4], c = x[n1 + 8], d = x[n1 + 12];
        bfly4p<INV>(a, b, c, d);
        u[n1 * 4 + 0] = a; u[n1 * 4 + 1] = b; u[n1 * 4 + 2] = c; u[n1 * 4 + 3] = d;
    }
    tw16<INV>(u);
    #pragma unroll
    for (int k1 = 0; k1 < 4; k1++) {
        ull a = u[k1], b = u[4 + k1], c = u[8 + k1], d = u[12 + k1];
        bfly4p<INV>(a, b, c, d);
        x[k1] = a; x[k1 + 4] = b; x[k1 + 8] = c; x[k1 + 12] = d;
    }
}

// Forward 16-pt DFT with x[8..15] == 0 (only x[0..7] read; all 16 written).
__device__ __forceinline__ void dft16ph(ull* x) {
    ull u[16];
    #pragma unroll
    for (int n1 = 0; n1 < 4; n1++) {
        ull a = x[n1], b = x[n1 + 4];      // c = d = 0
        ull jb = pmulj<0>(b);
        u[n1 * 4 + 0] = padd(a, b);
        u[n1 * 4 + 2] = psub(a, b);
        u[n1 * 4 + 1] = padd(a, jb);
        u[n1 * 4 + 3] = psub(a, jb);
    }
    tw16<0>(u);
    #pragma unroll
    for (int k1 = 0; k1 < 4; k1++) {
        ull a = u[k1], b = u[4 + k1], c = u[8 + k1], d = u[12 + k1];
        bfly4p<0>(a, b, c, d);
        x[k1] = a; x[k1 + 4] = b; x[k1 + 8] = c; x[k1 + 12] = d;
    }
}

// apply twiddle chain r[q] *= w^q, q = 1..15, w = (wx, wy)
__device__ __forceinline__ void twchain(ull* r, float wx, float wy) {
    float px = wx, py = wy;
    #pragma unroll
    for (int q = 1; q < 16; q++) {
        r[q] = pcmulf(r[q], px, py);
        float nx = px * wx - py * wy;
        float ny = px * wy + py * wx;
        px = nx; py = ny;
    }
}

#define ANG1 (-1.5339807878856412e-3f)   // -2*pi/4096
#define ANG2 (-2.4543692606170259e-2f)   // -2*pi/256

// ---------------------------------------------------------------------------
// N=4096 radix-16 FFT, 256 threads, 16 packed complex in registers/thread.
// fwd: natural in (r[q] = x[t+256q], upper half zero) -> thread t holds
// digit-reversed slots 16t+q.  inv mirrors back to natural.
// ---------------------------------------------------------------------------
__device__ __forceinline__ void fft4096_fwd(ull* r, ull* sh, int t) {
    const int o = t & 15, b = t >> 4;
    dft16ph(r);
    { float sy, cx; __sincosf(ANG1 * (float)t, &sy, &cx); twchain(r, cx, sy); }
    #pragma unroll
    for (int q = 0; q < 16; q++) sh[PITCH * q + t] = r[q];
    __syncthreads();
    #pragma unroll
    for (int m = 0; m < 16; m++) r[m] = sh[PITCH * b + 16 * m + o];
    dft16p<0>(r);
    { float sy, cx; __sincosf(ANG2 * (float)o, &sy, &cx); twchain(r, cx, sy); }
    __syncthreads();
    #pragma unroll
    for (int q = 0; q < 16; q++) sh[PITCH * b + 17 * q + o] = r[q];
    __syncthreads();
    #pragma unroll
    for (int j = 0; j < 16; j++) r[j] = sh[PITCH * b + 17 * o + j];
    dft16p<0>(r);
}

__device__ __forceinline__ void fft4096_inv(ull* r, ull* sh, int t) {
    const int o = t & 15, b = t >> 4;
    dft16p<1>(r);
    __syncthreads();
    #pragma unroll
    for (int j = 0; j < 16; j++) sh[PITCH * b + 17 * o + j] = r[j];
    __syncthreads();
    #pragma unroll
    for (int q = 0; q < 16; q++) r[q] = sh[PITCH * b + 17 * q + o];
    { float sy, cx; __sincosf(-ANG2 * (float)o, &sy, &cx); twchain(r, cx, sy); }
    dft16p<1>(r);
    __syncthreads();
    #pragma unroll
    for (int m = 0; m < 16; m++) sh[PITCH * b + 16 * m + o] = r[m];
    __syncthreads();
    #pragma unroll
    for (int q = 0; q < 16; q++) r[q] = sh[PITCH * q + t];
    { float sy, cx; __sincosf(-ANG1 * (float)t, &sy, &cx); twchain(r, cx, sy); }
    dft16p<1>(r);
}

// ---------------------------------------------------------------------------
// K1: filter build + FFT, one head per 256-thread block.
// Recurrence: h_0 = 1; h_t = sum_j w_j h_{t-1-j}.  f = g (*) h.
// h built via resolvent doubling (bootstrap) + 31 blocked-IIR chunks.
// ---------------------------------------------------------------------------
__global__ __launch_bounds__(256) void filter_fft_kernel(const float* __restrict__ kin) {
    __shared__ float sw[64], sg[64], sP[64], skn[64], soldc[64], spart[2];
    __shared__ float hsh[2048];
    __shared__ ull  exch[16 * PITCH];

    const int tid = threadIdx.x;
    const int h   = blockIdx.x;
    float kv = 0.f;

    if (tid < 64) {
        kv = kin[h * NK + tid];
        float kc = fminf(fmaxf(kv, 0.0625f), 1.0f);
        float v = kc;
        #pragma unroll
        for (int o = 16; o; o >>= 1) v += __shfl_xor_sync(0xffffffffu, v, o);
        if ((tid & 31) == 0) spart[tid >> 5] = v;
        skn[tid] = kc;   // temp: clipped value
    }
    __syncthreads();
    if (tid < 64) skn[tid] = skn[tid] / (spart[0] + spart[1]);
    __syncthreads();
    if (tid == 0) {
        float p = 1.0f;
        #pragma unroll 8
        for (int j = 0; j < 64; j++) {
            sP[j] = p;
            if (j < 63) p *= 1.0f / (1.0f + skn[j]);
        }
    }
    __syncthreads();
    if (tid < 64) {
        float kn = skn[tid];
        float m0 = (tid < 63) ? kn / (1.0f + kn) : 1.0f;
        sw[tid] = m0 * sP[tid];
        sg[tid] = kv * sP[tid];
    }
    __syncthreads();

    // ---- bootstrap h[0..63] (warp 0 only): doubling with resolvent trick
    if (tid < 32) {
        if (tid == 0) hsh[0] = 1.0f;
        __syncwarp();
        #pragma unroll
        for (int s = 1; s <= 32; s <<= 1) {
            if (tid < s) {
                const int r = tid;
                float oc = 0.f;
                for (int j = r; j < s + r; j++) oc += sw[j] * hsh[s + r - 1 - j];
                soldc[r] = oc;
            }
            __syncwarp();
            if (tid < s) {
                const int r = tid;
                float nv = 0.f;
                for (int m = 0; m <= r; m++) nv += hsh[r - m] * soldc[m];
                hsh[s + r] = nv;
            }
            __syncwarp();
        }
    }
    __syncthreads();

    // ---- 31 chunks of 64: old contribution then resolvent solve
    for (int p = 64; p < 2048; p += 64) {
        if (tid < 64) {
            const int r = tid;
            float oc = 0.f;
            for (int j = r; j < 64; j++) oc += sw[j] * hsh[p + r - 1 - j];
            soldc[r] = oc;
        }
        __syncthreads();
        if (tid < 64) {
            const int r = tid;
            float nv = 0.f;
            for (int m = 0; m <= r; m++) nv += hsh[r - m] * soldc[m];
            hsh[p + r] = nv;
        }
        __syncthreads();
    }

    // ---- f_t = sum_i g_i h_{t-i}, computed straight into FFT input registers
    ull r[16];
    {   // q = 0: t = tid < 256, guard i <= t (only matters for tid < 63)
        const int t = tid;
        float acc = 0.f;
        #pragma unroll
        for (int i = 0; i < 64; i++)
            if (i <= t) acc += sg[i] * hsh[t - i];
        r[0] = pk2(acc * (1.0f / NFFT), 0.f);
    }
    #pragma unroll
    for (int q = 1; q < 8; q++) {
        const int t = tid + 256 * q;
        float a0 = 0.f, a1 = 0.f, a2 = 0.f, a3 = 0.f;
        #pragma unroll
        for (int i = 0; i < 64; i += 4) {
            a0 += sg[i + 0] * hsh[t - i - 0];
            a1 += sg[i + 1] * hsh[t - i - 1];
            a2 += sg[i + 2] * hsh[t - i - 2];
            a3 += sg[i + 3] * hsh[t - i - 3];
        }
        r[q] = pk2(((a0 + a1) + (a2 + a3)) * (1.0f / NFFT), 0.f);
    }

    fft4096_fwd(r, exch, tid);

    #pragma unroll
    for (int q = 0; q < 16; q++)
        d_Fhat[(size_t)h * NFFT + q * 256 + tid] = r[q];
}

// ---------------------------------------------------------------------------
// K2: FFT convolution, two batches packed per complex FFT.
// ---------------------------------------------------------------------------
__global__ __launch_bounds__(256) void conv_kernel(const float* __restrict__ u,
                                                   float* __restrict__ y) {
    __shared__ ull exch[16 * PITCH];
    ull r[16];
    const int t  = threadIdx.x;
    const int h  = blockIdx.y;
    const int bp = blockIdx.x;
    const float* u0 = u + ((size_t)(2 * bp) * NHEADS + h) * SEQ;
    const float* u1 = u0 + (size_t)NHEADS * SEQ;

    #pragma unroll
    for (int q = 0; q < 8; q++) {
        int idx = t + 256 * q;
        r[q] = pk2(__ldg(&u0[idx]), __ldg(&u1[idx]));
    }

    fft4096_fwd(r, exch, t);

    const ull* Fh = d_Fhat + (size_t)h * NFFT;
    #pragma unroll
    for (int q = 0; q < 16; q++) {
        float fx, fy; unpk2(__ldg(&Fh[q * 256 + t]), fx, fy);
        r[q] = pcmulf(r[q], fx, fy);
    }

    fft4096_inv(r, exch, t);

    float* y0 = y + ((size_t)(2 * bp) * NHEADS + h) * SEQ;
    float* y1 = y0 + (size_t)NHEADS * SEQ;
    #pragma unroll
    for (int m = 0; m < 8; m++) {
        int idx = t + 256 * m;
        float a, b; unpk2(r[m], a, b);
        y0[idx] = a;
        y1[idx] = b;
    }
}

// ---------------------------------------------------------------------------
extern "C" void kernel_launch(void* const* d_in, const int* in_sizes, int n_in,
                              void* d_out, int out_size) {
    const float* u = (const float*)d_in[0];
    const float* k = (const float*)d_in[1];
    if (n_in >= 2 && in_sizes[0] < in_sizes[1]) {
        const float* t = u; u = k; k = t;
    }
    float* y = (float*)d_out;

    filter_fft_kernel<<<NHEADS, 256>>>(k);
    conv_kernel<<<dim3(NB / 2, NHEADS), 256>>>(u, y);
}

// round 5
// speedup vs baseline: 1.7358x; 1.7358x over previous
#include <cuda_runtime.h>
#include <cuda_bf16.h>

#define NHEADS 512
#define NK     64
#define SEQ    2048
#define NFFT   4096
#define NB     16
#define PITCH  272   // transpose pitch: 16*17, conflict-free for both patterns

typedef unsigned long long ull;

// Scratch (static __device__ — no allocation)
__device__ float d_f[NHEADS * SEQ];
__device__ ull   d_Fhat[NHEADS * NFFT];   // packed complex, layout [h][q*256+t]

// ---------------------------------------------------------------------------
// Packed f32x2 complex helpers (value = ull, lo 32b = re, hi 32b = im)
// ---------------------------------------------------------------------------
__device__ __forceinline__ ull pk2(float x, float y) {
    ull r; asm("mov.b64 %0, {%1, %2};" : "=l"(r) : "f"(x), "f"(y)); return r;
}
__device__ __forceinline__ void unpk2(ull a, float& x, float& y) {
    asm("mov.b64 {%0, %1}, %2;" : "=f"(x), "=f"(y) : "l"(a));
}
__device__ __forceinline__ ull padd(ull a, ull b) {
    ull r; asm("add.rn.f32x2 %0, %1, %2;" : "=l"(r) : "l"(a), "l"(b)); return r;
}
__device__ __forceinline__ ull psub(ull a, ull b) {   // a - b  via fma(b, -1, a)
    const ull m1 = 0xBF800000BF800000ULL;
    ull r; asm("fma.rn.f32x2 %0, %1, %2, %3;" : "=l"(r) : "l"(b), "l"(m1), "l"(a)); return r;
}
__device__ __forceinline__ float fneg(float x) {
    return __int_as_float(__float_as_int(x) ^ 0x80000000);
}
// multiply by -i (fwd) or +i (inv)
template<int INV>
__device__ __forceinline__ ull pmulj(ull a) {
    float x, y; unpk2(a, x, y);
    return INV ? pk2(fneg(y), x) : pk2(y, fneg(x));
}
// packed a times scalar complex (wx, wy)
__device__ __forceinline__ ull pcmulf(ull a, float wx, float wy) {
    float x, y; unpk2(a, x, y);
    return pk2(fmaf(x, wx, -(y * wy)), fmaf(x, wy, y * wx));
}

template<int INV>
__device__ __forceinline__ void bfly4p(ull& x0, ull& x1, ull& x2, ull& x3) {
    ull ac = padd(x0, x2), amc = psub(x0, x2);
    ull bd = padd(x1, x3), bmd = psub(x1, x3);
    ull jb = pmulj<INV>(bmd);
    x0 = padd(ac, bd);  x2 = psub(ac, bd);
    x1 = padd(amc, jb); x3 = psub(amc, jb);
}

// twiddle application W16^{n1*k1} (sign via INV); literal constants so ptxas
// can use the imm-form FFMA (2x issue rate).
template<int INV>
__device__ __forceinline__ void tw16(ull* u) {
    const float C1 = 0.9238795325112867f, S1 = 0.3826834323650898f, R = 0.7071067811865476f;
    const float s = INV ? 1.0f : -1.0f;
    u[5]  = pcmulf(u[5],   C1,  s * S1);
    u[6]  = pcmulf(u[6],    R,  s * R);
    u[7]  = pcmulf(u[7],   S1,  s * C1);
    u[9]  = pcmulf(u[9],    R,  s * R);
    u[10] = pmulj<INV>(u[10]);
    u[11] = pcmulf(u[11],  -R,  s * R);
    u[13] = pcmulf(u[13],  S1,  s * C1);
    u[14] = pcmulf(u[14],  -R,  s * R);
    u[15] = pcmulf(u[15], -C1, -s * S1);
}

// Full in-place 16-pt DFT (x[n] -> X[k] at x[k]); INV=1 un-normalized inverse.
template<int INV>
__device__ __forceinline__ void dft16p(ull* x) {
    ull u[16];
    #pragma unroll
    for (int n1 = 0; n1 < 4; n1++) {
        ull a = x[n1], b = x[n1 + 4], c = x[n1 + 8], d = x[n1 + 12];
        bfly4p<INV>(a, b, c, d);
        u[n1 * 4 + 0] = a; u[n1 * 4 + 1] = b; u[n1 * 4 + 2] = c; u[n1 * 4 + 3] = d;
    }
    tw16<INV>(u);
    #pragma unroll
    for (int k1 = 0; k1 < 4; k1++) {
        ull a = u[k1], b = u[4 + k1], c = u[8 + k1], d = u[12 + k1];
        bfly4p<INV>(a, b, c, d);
        x[k1] = a; x[k1 + 4] = b; x[k1 + 8] = c; x[k1 + 12] = d;
    }
}

// Forward 16-pt DFT with x[8..15] == 0 (only x[0..7] read; all 16 written).
__device__ __forceinline__ void dft16ph(ull* x) {
    ull u[16];
    #pragma unroll
    for (int n1 = 0; n1 < 4; n1++) {
        ull a = x[n1], b = x[n1 + 4];      // c = d = 0
        ull jb = pmulj<0>(b);
        u[n1 * 4 + 0] = padd(a, b);
        u[n1 * 4 + 2] = psub(a, b);
        u[n1 * 4 + 1] = padd(a, jb);
        u[n1 * 4 + 3] = psub(a, jb);
    }
    tw16<0>(u);
    #pragma unroll
    for (int k1 = 0; k1 < 4; k1++) {
        ull a = u[k1], b = u[4 + k1], c = u[8 + k1], d = u[12 + k1];
        bfly4p<0>(a, b, c, d);
        x[k1] = a; x[k1 + 4] = b; x[k1 + 8] = c; x[k1 + 12] = d;
    }
}

// apply twiddle chain r[q] *= w^q, q = 1..15, w = (wx, wy)
__device__ __forceinline__ void twchain(ull* r, float wx, float wy) {
    float px = wx, py = wy;
    #pragma unroll
    for (int q = 1; q < 16; q++) {
        r[q] = pcmulf(r[q], px, py);
        float nx = px * wx - py * wy;
        float ny = px * wy + py * wx;
        px = nx; py = ny;
    }
}

#define ANG1 (-1.5339807878856412e-3f)   // -2*pi/4096
#define ANG2 (-2.4543692606170259e-2f)   // -2*pi/256

// ---------------------------------------------------------------------------
// N=4096 radix-16 FFT, 256 threads, 16 packed complex in registers/thread.
// fwd: natural in (r[q] = x[t+256q], upper half zero) -> thread t holds
// digit-reversed slots 16t+q.  inv mirrors back to natural.
// ---------------------------------------------------------------------------
__device__ __forceinline__ void fft4096_fwd(ull* r, ull* sh, int t) {
    const int o = t & 15, b = t >> 4;
    dft16ph(r);
    { float sy, cx; __sincosf(ANG1 * (float)t, &sy, &cx); twchain(r, cx, sy); }
    #pragma unroll
    for (int q = 0; q < 16; q++) sh[PITCH * q + t] = r[q];
    __syncthreads();
    #pragma unroll
    for (int m = 0; m < 16; m++) r[m] = sh[PITCH * b + 16 * m + o];
    dft16p<0>(r);
    { float sy, cx; __sincosf(ANG2 * (float)o, &sy, &cx); twchain(r, cx, sy); }
    __syncthreads();
    #pragma unroll
    for (int q = 0; q < 16; q++) sh[PITCH * b + 17 * q + o] = r[q];
    __syncthreads();
    #pragma unroll
    for (int j = 0; j < 16; j++) r[j] = sh[PITCH * b + 17 * o + j];
    dft16p<0>(r);
}

__device__ __forceinline__ void fft4096_inv(ull* r, ull* sh, int t) {
    const int o = t & 15, b = t >> 4;
    dft16p<1>(r);
    __syncthreads();
    #pragma unroll
    for (int j = 0; j < 16; j++) sh[PITCH * b + 17 * o + j] = r[j];
    __syncthreads();
    #pragma unroll
    for (int q = 0; q < 16; q++) r[q] = sh[PITCH * b + 17 * q + o];
    { float sy, cx; __sincosf(-ANG2 * (float)o, &sy, &cx); twchain(r, cx, sy); }
    dft16p<1>(r);
    __syncthreads();
    #pragma unroll
    for (int m = 0; m < 16; m++) sh[PITCH * b + 16 * m + o] = r[m];
    __syncthreads();
    #pragma unroll
    for (int q = 0; q < 16; q++) r[q] = sh[PITCH * q + t];
    { float sy, cx; __sincosf(-ANG1 * (float)t, &sy, &cx); twchain(r, cx, sy); }
    dft16p<1>(r);
}

// ---------------------------------------------------------------------------
// Filter construction (R3 proven version: matrix-power T = C^64).
// ---------------------------------------------------------------------------
__global__ __launch_bounds__(64) void filter_kernel(const float* __restrict__ kin) {
    __shared__ float sh_kn[64], sh_P[64], sh_w[64], sh_g[64];
    __shared__ float sh_T[64 * 65];
    __shared__ float sh_V[64];
    __shared__ float sh_a[2048];
    __shared__ float part[2];

    const int tid = threadIdx.x;
    const int h   = blockIdx.x;

    float kv = kin[h * NK + tid];
    float kc = fminf(fmaxf(kv, 0.0625f), 1.0f);

    float v = kc;
    #pragma unroll
    for (int o = 16; o; o >>= 1) v += __shfl_xor_sync(0xffffffffu, v, o);
    if ((tid & 31) == 0) part[tid >> 5] = v;
    __syncthreads();
    float kn = kc / (part[0] + part[1]);
    sh_kn[tid] = kn;
    __syncthreads();

    if (tid == 0) {
        float p = 1.0f;
        for (int j = 0; j < 64; j++) {
            sh_P[j] = p;
            if (j < 63) p *= 1.0f / (1.0f + sh_kn[j]);
        }
    }
    __syncthreads();

    float m0 = (tid < 63) ? kn / (1.0f + kn) : 1.0f;
    sh_w[tid] = m0 * sh_P[tid];
    sh_g[tid] = kv * sh_P[tid];
    __syncthreads();

    // Phase A: columns of T = C^64. Thread `tid` rolls out impulse e_tid.
    float wr[64];
    #pragma unroll
    for (int i = 0; i < 64; i++) wr[i] = sh_w[i];

    float win[64];
    const int seed = (64 - tid) & 63;
    #pragma unroll
    for (int p = 0; p < 64; p++) win[p] = (p == seed) ? 1.0f : 0.0f;

    #pragma unroll
    for (int t = 0; t < 64; t++) {
        float n0 = 0.f, n1 = 0.f, n2 = 0.f, n3 = 0.f;
        #pragma unroll
        for (int i = 0; i < 64; i += 4) {
            n0 += wr[i + 0] * win[(t - i - 0) & 63];
            n1 += wr[i + 1] * win[(t - i - 1) & 63];
            n2 += wr[i + 2] * win[(t - i - 2) & 63];
            n3 += wr[i + 3] * win[(t - i - 3) & 63];
        }
        win[(t + 1) & 63] = (n0 + n1) + (n2 + n3);
    }
    #pragma unroll
    for (int i = 0; i < 64; i++) sh_T[i * 65 + tid] = win[(64 - i) & 63];
    __syncthreads();

    // Phase B: 32 chunk matvecs
    sh_V[tid] = (tid == 0) ? 1.0f : 0.0f;
    if (tid == 0) sh_a[0] = 1.0f;
    __syncthreads();

    for (int m = 0; m < 32; m++) {
        float n0 = 0.f, n1 = 0.f, n2 = 0.f, n3 = 0.f;
        #pragma unroll
        for (int j = 0; j < 64; j += 4) {
            n0 += sh_T[tid * 65 + j + 0] * sh_V[j + 0];
            n1 += sh_T[tid * 65 + j + 1] * sh_V[j + 1];
            n2 += sh_T[tid * 65 + j + 2] * sh_V[j + 2];
            n3 += sh_T[tid * 65 + j + 3] * sh_V[j + 3];
        }
        float nv = (n0 + n1) + (n2 + n3);
        __syncthreads();
        sh_V[tid] = nv;
        int idx = 64 * m + 64 - tid;
        if (idx < 2048) sh_a[idx] = nv;
        __syncthreads();
    }

    // Phase C: f_t = sum_i g[i] a_{t-i}  (1/NFFT folded in here)
    float gr[64];
    #pragma unroll
    for (int i = 0; i < 64; i++) gr[i] = sh_g[i];

    {
        int t = tid;
        float acc = 0.f;
        #pragma unroll
        for (int i = 0; i < 64; i++)
            if (i <= t) acc += gr[i] * sh_a[t - i];
        d_f[h * SEQ + t] = acc * (1.0f / NFFT);
    }
    for (int q = 1; q < 32; q++) {
        int t = q * 64 + tid;
        float a0 = 0.f, a1 = 0.f, a2 = 0.f, a3 = 0.f;
        #pragma unroll
        for (int i = 0; i < 64; i += 4) {
            a0 += gr[i + 0] * sh_a[t - i - 0];
            a1 += gr[i + 1] * sh_a[t - i - 1];
            a2 += gr[i + 2] * sh_a[t - i - 2];
            a3 += gr[i + 3] * sh_a[t - i - 3];
        }
        d_f[h * SEQ + t] = ((a0 + a1) + (a2 + a3)) * (1.0f / NFFT);
    }
}

// ---------------------------------------------------------------------------
// Filter spectrum (packed), layout [h][q*256+t]; 1/N already folded into d_f.
// ---------------------------------------------------------------------------
__global__ __launch_bounds__(256) void fft_filter_kernel() {
    __shared__ ull exch[16 * PITCH];
    ull r[16];
    const int t = threadIdx.x, h = blockIdx.x;

    #pragma unroll
    for (int q = 0; q < 8; q++)
        r[q] = pk2(d_f[h * SEQ + t + 256 * q], 0.f);

    fft4096_fwd(r, exch, t);

    #pragma unroll
    for (int q = 0; q < 16; q++)
        d_Fhat[(size_t)h * NFFT + q * 256 + t] = r[q];
}

// ---------------------------------------------------------------------------
// Convolution: two batches packed per complex FFT.
// ---------------------------------------------------------------------------
__global__ __launch_bounds__(256, 4) void conv_kernel(const float* __restrict__ u,
                                                      float* __restrict__ y) {
    __shared__ ull exch[16 * PITCH];
    ull r[16];
    const int t  = threadIdx.x;
    const int h  = blockIdx.y;
    const int bp = blockIdx.x;
    const float* u0 = u + ((size_t)(2 * bp) * NHEADS + h) * SEQ;
    const float* u1 = u0 + (size_t)NHEADS * SEQ;

    #pragma unroll
    for (int q = 0; q < 8; q++) {
        int idx = t + 256 * q;
        r[q] = pk2(__ldg(&u0[idx]), __ldg(&u1[idx]));
    }

    fft4096_fwd(r, exch, t);

    const ull* Fh = d_Fhat + (size_t)h * NFFT;
    #pragma unroll
    for (int q = 0; q < 16; q++) {
        float fx, fy; unpk2(__ldg(&Fh[q * 256 + t]), fx, fy);
        r[q] = pcmulf(r[q], fx, fy);
    }

    fft4096_inv(r, exch, t);

    float* y0 = y + ((size_t)(2 * bp) * NHEADS + h) * SEQ;
    float* y1 = y0 + (size_t)NHEADS * SEQ;
    #pragma unroll
    for (int m = 0; m < 8; m++) {
        int idx = t + 256 * m;
        float a, b; unpk2(r[m], a, b);
        y0[idx] = a;
        y1[idx] = b;
    }
}

// ---------------------------------------------------------------------------
extern "C" void kernel_launch(void* const* d_in, const int* in_sizes, int n_in,
                              void* d_out, int out_size) {
    const float* u = (const float*)d_in[0];
    const float* k = (const float*)d_in[1];
    if (n_in >= 2 && in_sizes[0] < in_sizes[1]) {
        const float* t = u; u = k; k = t;
    }
    float* y = (float*)d_out;

    filter_kernel<<<NHEADS, 64>>>(k);
    fft_filter_kernel<<<NHEADS, 256>>>();
    conv_kernel<<<dim3(NB / 2, NHEADS), 256>>>(u, y);
}